// round 4
// baseline (speedup 1.0000x reference)
#include <cuda_runtime.h>

#define NANCH 19200      // 3*80*80 anchors per image
#define NIMG  8
#define MTGT  100
#define NCLS  80
#define THREADS 128
#define NWARP (THREADS / 32)
#define ANCH_PER_BLK THREADS                // 128, 1 anchor per thread
#define NBLK_PER_IMG (NANCH / ANCH_PER_BLK) // 150
#define NBLOCKS (NIMG * NBLK_PER_IMG)       // 1200

__device__ float    g_part[NBLOCKS * 4];
__device__ unsigned g_count;

__global__ void __launch_bounds__(THREADS) loss_fused(
    const float* __restrict__ obj,    // [8,19200]
    const float* __restrict__ boxes,  // [8,19200,4] (cx,cy,w,h)
    const float* __restrict__ cls,    // [8,19200,80]
    const float* __restrict__ tbox,   // [8,100,4]
    const int*   __restrict__ tlab,   // [8,100]
    float*       __restrict__ out)
{
    __shared__ float4 s_lohi[MTGT];          // lox,loy,hix,hiy
    __shared__ float  s_area[MTGT];
    __shared__ int    s_lab[MTGT];
    __shared__ int    s_pos_row[THREADS];    // global anchor row of positives
    __shared__ int    s_pos_lab[THREADS];
    __shared__ float  s_pos_giou[THREADS];   // (1 - giou) per positive
    __shared__ int    s_wtot[NWARP];
    __shared__ float  s_red[NWARP];
    __shared__ float  s_img[NIMG][4];
    __shared__ unsigned s_is_last;

    const int tid  = threadIdx.x;
    const int lane = tid & 31;
    const int wid  = tid >> 5;
    const int img  = blockIdx.x / NBLK_PER_IMG;
    const int ablk = blockIdx.x % NBLK_PER_IMG;
    const int row  = img * NANCH + ablk * ANCH_PER_BLK + tid;

    // ── Targets to shared ──
    if (tid < MTGT) {
        float4 tb = ((const float4*)tbox)[img * MTGT + tid];
        s_lohi[tid] = make_float4(tb.x - 0.5f * tb.z, tb.y - 0.5f * tb.w,
                                  tb.x + 0.5f * tb.z, tb.y + 0.5f * tb.w);
        s_area[tid] = tb.z * tb.w;
        s_lab[tid]  = tlab[img * MTGT + tid];
    }
    __syncthreads();

    // ── Anchor box ──
    float4 bx = ((const float4*)boxes)[row];
    const float lo1x = bx.x - 0.5f * bx.z, lo1y = bx.y - 0.5f * bx.w;
    const float hi1x = bx.x + 0.5f * bx.z, hi1y = bx.y + 0.5f * bx.w;
    const float a1   = bx.z * bx.w;

    // ── Phase 1: positivity only. iou>=0.5 <=> 3*inter >= a1+ta+1e-6 ──
    float maxd = -1e30f;
    #pragma unroll 4
    for (int m = 0; m < MTGT; m++) {
        float4 t  = s_lohi[m];
        float  ta = s_area[m];
        float wx = fmaxf(fminf(hi1x, t.z) - fmaxf(lo1x, t.x), 0.0f);
        float wy = fmaxf(fminf(hi1y, t.w) - fmaxf(lo1y, t.y), 0.0f);
        float d  = fmaf(3.0f, wx * wy, -(a1 + ta));
        maxd = fmaxf(maxd, d);
    }
    const bool pos = (maxd >= 1e-6f);

    // ── Objectness BCE ──
    float o = obj[row];
    float bce = pos ? -fmaxf(__logf(o), -100.0f)
                    : -fmaxf(__logf(1.0f - o), -100.0f);
    float posf = pos ? 1.0f : 0.0f;

    // ── Deterministic compaction of positives ──
    unsigned ball = __ballot_sync(0xFFFFFFFFu, pos);
    if (lane == 0) s_wtot[wid] = __popc(ball);
    __syncthreads();
    int wbase = 0, P = 0;
    #pragma unroll
    for (int w = 0; w < NWARP; w++) {
        wbase += (w < wid) ? s_wtot[w] : 0;
        P += s_wtot[w];
    }
    if (pos) {
        int ofs = wbase + __popc(ball & ((1u << lane) - 1u));
        s_pos_row[ofs] = row;
    }
    __syncthreads();

    // ── Phase 2: exact argmax + GIoU + label, one warp per positive ──
    for (int p = wid; p < P; p += NWARP) {
        int prow = s_pos_row[p];
        float4 pb = ((const float4*)boxes)[prow];   // broadcast within warp
        float plox = pb.x - 0.5f * pb.z, ploy = pb.y - 0.5f * pb.w;
        float phix = pb.x + 0.5f * pb.z, phiy = pb.y + 0.5f * pb.w;
        float pa   = pb.z * pb.w;

        float bi = -1.0f, bu = 1.0f;
        int   bidx = MTGT;
        #pragma unroll
        for (int k = 0; k < 4; k++) {
            int m = lane + k * 32;
            if (m < MTGT) {
                float4 t = s_lohi[m];
                float wx = fmaxf(fminf(phix, t.z) - fmaxf(plox, t.x), 0.0f);
                float wy = fmaxf(fminf(phiy, t.w) - fmaxf(ploy, t.y), 0.0f);
                float inter = wx * wy;
                float u = pa + s_area[m] - inter + 1e-6f;
                if (inter * bu > bi * u) { bi = inter; bu = u; bidx = m; }
            }
        }
        // warp argmax reduce (tie -> lower index, matching argmax-first)
        #pragma unroll
        for (int off = 16; off > 0; off >>= 1) {
            float bi2 = __shfl_down_sync(0xFFFFFFFFu, bi, off);
            float bu2 = __shfl_down_sync(0xFFFFFFFFu, bu, off);
            int   bx2 = __shfl_down_sync(0xFFFFFFFFu, bidx, off);
            float l = bi2 * bu, r = bi * bu2;
            bool take = (l > r) || (l == r && bx2 < bidx);
            if (take) { bi = bi2; bu = bu2; bidx = bx2; }
        }
        if (lane == 0) {
            float4 t = s_lohi[bidx];
            float wx = fmaxf(fminf(phix, t.z) - fmaxf(plox, t.x), 0.0f);
            float wy = fmaxf(fminf(phiy, t.w) - fmaxf(ploy, t.y), 0.0f);
            float inter = wx * wy;
            float uni = pa + s_area[bidx] - inter;
            float iou = __fdividef(inter, uni + 1e-6f);
            float ex = fmaxf(fmaxf(phix, t.z) - fminf(plox, t.x), 0.0f);
            float ey = fmaxf(fmaxf(phiy, t.w) - fminf(ploy, t.y), 0.0f);
            float enc = ex * ey;
            s_pos_giou[p] = 1.0f - (iou - __fdividef(enc - uni, enc + 1e-6f));
            s_pos_lab[p]  = s_lab[bidx];
        }
    }
    __syncthreads();

    float bbox = (tid < P) ? s_pos_giou[tid] : 0.0f;

    // ── Focal loss over positives (P*80 items, cooperative) ──
    float fl = 0.0f;
    const int items = P * NCLS;
    for (int i = tid; i < items; i += THREADS) {
        int a = i / NCLS;
        int ccol = i - a * NCLS;
        float x = cls[s_pos_row[a] * NCLS + ccol];
        bool t = (ccol == s_pos_lab[a]);
        float e  = __expf(-fabsf(x));
        float sp = __logf(1.0f + e);
        float s  = __fdividef(1.0f, 1.0f + e);
        float p  = (x >= 0.0f) ? s : (1.0f - s);
        float one_m_pt = t ? (1.0f - p) : p;
        float ce = sp + fmaxf(t ? -x : x, 0.0f);
        float at = t ? 0.25f : 0.75f;
        fl += at * one_m_pt * one_m_pt * ce;
    }

    // ── block reduction of (bce, posf, bbox, fl) — deterministic ──
    float vals[4] = {bce, posf, bbox, fl};
    #pragma unroll
    for (int k = 0; k < 4; k++) {
        float v = vals[k];
        #pragma unroll
        for (int off = 16; off > 0; off >>= 1)
            v += __shfl_down_sync(0xFFFFFFFFu, v, off);
        if (lane == 0) s_red[wid] = v;
        __syncthreads();
        if (tid == 0) {
            float r = 0.0f;
            #pragma unroll
            for (int w = 0; w < NWARP; w++) r += s_red[w];
            g_part[blockIdx.x * 4 + k] = r;
        }
        __syncthreads();
    }

    // ── last-block finalize ──
    __threadfence();
    if (tid == 0) s_is_last = (atomicAdd(&g_count, 1) == NBLOCKS - 1) ? 1u : 0u;
    __syncthreads();
    if (!s_is_last) return;
    __threadfence();

    {
        int fimg = tid >> 4;        // 0..7 (128 threads = 8 imgs x 16 slots)
        int sub  = tid & 15;        // 0..15
        float v0 = 0, v1 = 0, v2 = 0, v3 = 0;
        for (int s = sub; s < NBLK_PER_IMG; s += 16) {
            int b = fimg * NBLK_PER_IMG + s;
            v0 += g_part[b * 4 + 0];
            v1 += g_part[b * 4 + 1];
            v2 += g_part[b * 4 + 2];
            v3 += g_part[b * 4 + 3];
        }
        #pragma unroll
        for (int off = 8; off > 0; off >>= 1) {
            v0 += __shfl_down_sync(0xFFFFFFFFu, v0, off, 16);
            v1 += __shfl_down_sync(0xFFFFFFFFu, v1, off, 16);
            v2 += __shfl_down_sync(0xFFFFFFFFu, v2, off, 16);
            v3 += __shfl_down_sync(0xFFFFFFFFu, v3, off, 16);
        }
        if (sub == 0) {
            s_img[fimg][0] = v0; s_img[fimg][1] = v1;
            s_img[fimg][2] = v2; s_img[fimg][3] = v3;
        }
        __syncthreads();
        if (tid == 0) {
            float obj_sum = 0, bbox_sum = 0, cls_sum = 0, num_pos = 0;
            #pragma unroll
            for (int i = 0; i < NIMG; i++) {
                float bces = s_img[i][0];
                float pc   = s_img[i][1];
                float bb   = s_img[i][2];
                float fls  = s_img[i][3];
                obj_sum  += bces * (1.0f * pc + 0.5f * ((float)NANCH - pc));
                bbox_sum += bb;
                cls_sum  += fls / fmaxf(pc * (float)NCLS, 1.0f);
                num_pos  += pc;
            }
            num_pos = fmaxf(num_pos, 1.0f);
            out[0] = obj_sum / (float)NIMG
                   + 5.0f * bbox_sum / num_pos
                   + cls_sum / (float)NIMG;
            g_count = 0;   // reset for next graph replay
        }
    }
}

extern "C" void kernel_launch(void* const* d_in, const int* in_sizes, int n_in,
                              void* d_out, int out_size) {
    const float* obj   = (const float*)d_in[0];
    const float* boxes = (const float*)d_in[1];
    const float* cls   = (const float*)d_in[2];
    const float* tbox  = (const float*)d_in[3];
    const int*   tlab  = (const int*)d_in[4];
    float* out = (float*)d_out;

    loss_fused<<<NBLOCKS, THREADS>>>(obj, boxes, cls, tbox, tlab, out);
}

// round 5
// speedup vs baseline: 1.0702x; 1.0702x over previous
#include <cuda_runtime.h>

#define NANCH 19200      // 3*80*80 anchors per image
#define NIMG  8
#define MTGT  100
#define NCLS  80
#define THREADS 128
#define NWARP (THREADS / 32)
#define ANCH_PER_BLK THREADS                // 128, 1 anchor/thread
#define NBLK_PER_IMG (NANCH / ANCH_PER_BLK) // 150
#define NBLOCKS (NIMG * NBLK_PER_IMG)       // 1200

__device__ float    g_part[NBLOCKS * 4];
__device__ unsigned g_count;

__global__ void __launch_bounds__(THREADS) loss_fused(
    const float* __restrict__ obj,    // [8,19200]
    const float* __restrict__ boxes,  // [8,19200,4] (cx,cy,w,h)
    const float* __restrict__ cls,    // [8,19200,80]
    const float* __restrict__ tbox,   // [8,100,4]
    const int*   __restrict__ tlab,   // [8,100]
    float*       __restrict__ out)
{
    __shared__ float4 s_lohi[MTGT];          // lox,loy,hix,hiy
    __shared__ float  s_area[MTGT];
    __shared__ int    s_lab[MTGT];
    __shared__ int    s_pos_row[THREADS];    // global anchor row of positives
    __shared__ int    s_pos_lab[THREADS];
    __shared__ int    s_pos_tgt[THREADS];    // winning target idx
    __shared__ int    s_wtot[NWARP];
    __shared__ float  s_red[NWARP];
    __shared__ float  s_img[NIMG][4];
    __shared__ unsigned s_is_last;

    const int tid  = threadIdx.x;
    const int lane = tid & 31;
    const int wid  = tid >> 5;
    const int img  = blockIdx.x / NBLK_PER_IMG;
    const int ablk = blockIdx.x % NBLK_PER_IMG;
    const int row  = img * NANCH + ablk * ANCH_PER_BLK + tid;

    // ── Targets to shared ──
    if (tid < MTGT) {
        float4 tb = ((const float4*)tbox)[img * MTGT + tid];
        s_lohi[tid] = make_float4(tb.x - 0.5f * tb.z, tb.y - 0.5f * tb.w,
                                  tb.x + 0.5f * tb.z, tb.y + 0.5f * tb.w);
        s_area[tid] = tb.z * tb.w;
        s_lab[tid]  = tlab[img * MTGT + tid];
    }
    __syncthreads();

    // ── Anchor box ──
    float4 bx = ((const float4*)boxes)[row];
    const float lo1x = bx.x - 0.5f * bx.z, lo1y = bx.y - 0.5f * bx.w;
    const float hi1x = bx.x + 0.5f * bx.z, hi1y = bx.y + 0.5f * bx.w;
    const float a1   = bx.z * bx.w;

    // ── Single pass: packed argmax of x = inter/(a1+ta) (monotone in IoU).
    //    Index packed into mantissa low 7 bits; IMAX reduces; tie -> lower m.
    int vmax = (int)0x80000000;
    #pragma unroll 4
    for (int m = 0; m < MTGT; m++) {
        float4 t  = s_lohi[m];
        float  ta = s_area[m];
        float wx = fminf(hi1x, t.z) - fmaxf(lo1x, t.x);          // unclamped ok
        float wy = fmaxf(fminf(hi1y, t.w) - fmaxf(lo1y, t.y), 0.0f);
        float inter = wx * wy;
        float s  = a1 + ta;
        float x  = inter * __frcp_rn(s);   // want MUFU.RCP; see note below
        int pk = (__float_as_int(x) & (int)0xFFFFFF80) | (127 - m);
        vmax = max(vmax, pk);
    }
    const int bidx = 127 - (vmax & 127);

    // exact positivity confirm on the winner only: iou>=0.5 <=> 3*inter >= a1+ta+1e-6
    bool pos;
    {
        float4 t = s_lohi[bidx];
        float wx = fmaxf(fminf(hi1x, t.z) - fmaxf(lo1x, t.x), 0.0f);
        float wy = fmaxf(fminf(hi1y, t.w) - fmaxf(lo1y, t.y), 0.0f);
        float inter = wx * wy;
        pos = (3.0f * inter >= a1 + s_area[bidx] + 1e-6f);
    }
    const float posf = pos ? 1.0f : 0.0f;

    // ── Objectness BCE (single log on selected argument) ──
    float o = obj[row];
    float bce = -fmaxf(__logf(pos ? o : 1.0f - o), -100.0f);

    // ── Deterministic compaction of positives ──
    unsigned ball = __ballot_sync(0xFFFFFFFFu, pos);
    if (lane == 0) s_wtot[wid] = __popc(ball);
    __syncthreads();
    int wbase = 0, P = 0;
    #pragma unroll
    for (int w = 0; w < NWARP; w++) {
        wbase += (w < wid) ? s_wtot[w] : 0;
        P += s_wtot[w];
    }
    if (pos) {
        int ofs = wbase + __popc(ball & ((1u << lane) - 1u));
        s_pos_row[ofs] = row;
        s_pos_tgt[ofs] = bidx;
        s_pos_lab[ofs] = s_lab[bidx];
    }
    __syncthreads();

    // ── GIoU for positives, strided over threads (deterministic) ──
    float bbox = 0.0f;
    for (int i = tid; i < P; i += THREADS) {
        float4 pb = ((const float4*)boxes)[s_pos_row[i]];   // L1-hot
        float plox = pb.x - 0.5f * pb.z, ploy = pb.y - 0.5f * pb.w;
        float phix = pb.x + 0.5f * pb.z, phiy = pb.y + 0.5f * pb.w;
        float pa   = pb.z * pb.w;
        int   bm   = s_pos_tgt[i];
        float4 t = s_lohi[bm];
        float wx = fmaxf(fminf(phix, t.z) - fmaxf(plox, t.x), 0.0f);
        float wy = fmaxf(fminf(phiy, t.w) - fmaxf(ploy, t.y), 0.0f);
        float inter = wx * wy;
        float uni = pa + s_area[bm] - inter;
        float iou = __fdividef(inter, uni + 1e-6f);
        float ex = fmaxf(fmaxf(phix, t.z) - fminf(plox, t.x), 0.0f);
        float ey = fmaxf(fmaxf(phiy, t.w) - fminf(ploy, t.y), 0.0f);
        float enc = ex * ey;
        bbox += 1.0f - (iou - __fdividef(enc - uni, enc + 1e-6f));
    }

    // ── Focal loss over positives (P*80 items, incremental indexing) ──
    float fl = 0.0f;
    {
        const int items = P * NCLS;
        int a = 0, c = tid;
        if (c >= NCLS) { c -= NCLS; a += 1; }
        for (int i = tid; i < items; i += THREADS) {
            float x = cls[s_pos_row[a] * NCLS + c];
            bool t = (c == s_pos_lab[a]);
            float e  = __expf(-fabsf(x));
            float q  = 1.0f + e;
            float pabs = __fdividef(1.0f, q);          // sigmoid(|x|)
            float lg = __logf(q);                      // log1p(exp(-|x|))
            float p  = (x >= 0.0f) ? pabs : 1.0f - pabs;
            float omp = t ? (1.0f - p) : p;            // 1 - p_t
            float relu = fmaxf(t ? -x : x, 0.0f);
            float ce = lg + relu;
            float at = t ? 0.25f : 0.75f;
            fl += at * omp * omp * ce;
            c += THREADS - NCLS;                       // +48
            a += 1;
            if (c >= NCLS) { c -= NCLS; a += 1; }
        }
    }

    // ── block reduction of (bce, posf, bbox, fl) — deterministic ──
    float vals[4] = {bce, posf, bbox, fl};
    #pragma unroll
    for (int k = 0; k < 4; k++) {
        float v = vals[k];
        #pragma unroll
        for (int off = 16; off > 0; off >>= 1)
            v += __shfl_down_sync(0xFFFFFFFFu, v, off);
        if (lane == 0) s_red[wid] = v;
        __syncthreads();
        if (tid == 0) {
            float r = 0.0f;
            #pragma unroll
            for (int w = 0; w < NWARP; w++) r += s_red[w];
            g_part[blockIdx.x * 4 + k] = r;
        }
        __syncthreads();
    }

    // ── last-block finalize ──
    __threadfence();
    if (tid == 0) s_is_last = (atomicAdd(&g_count, 1) == NBLOCKS - 1) ? 1u : 0u;
    __syncthreads();
    if (!s_is_last) return;
    __threadfence();

    {
        int fimg = tid >> 4;        // 0..7 (128 threads = 8 imgs x 16 slots)
        int sub  = tid & 15;        // 0..15
        float v0 = 0, v1 = 0, v2 = 0, v3 = 0;
        for (int s = sub; s < NBLK_PER_IMG; s += 16) {
            int b = fimg * NBLK_PER_IMG + s;
            v0 += g_part[b * 4 + 0];
            v1 += g_part[b * 4 + 1];
            v2 += g_part[b * 4 + 2];
            v3 += g_part[b * 4 + 3];
        }
        #pragma unroll
        for (int off = 8; off > 0; off >>= 1) {
            v0 += __shfl_down_sync(0xFFFFFFFFu, v0, off, 16);
            v1 += __shfl_down_sync(0xFFFFFFFFu, v1, off, 16);
            v2 += __shfl_down_sync(0xFFFFFFFFu, v2, off, 16);
            v3 += __shfl_down_sync(0xFFFFFFFFu, v3, off, 16);
        }
        if (sub == 0) {
            s_img[fimg][0] = v0; s_img[fimg][1] = v1;
            s_img[fimg][2] = v2; s_img[fimg][3] = v3;
        }
        __syncthreads();
        if (tid == 0) {
            float obj_sum = 0, bbox_sum = 0, cls_sum = 0, num_pos = 0;
            #pragma unroll
            for (int i = 0; i < NIMG; i++) {
                float bces = s_img[i][0];
                float pc   = s_img[i][1];
                float bb   = s_img[i][2];
                float fls  = s_img[i][3];
                obj_sum  += bces * (1.0f * pc + 0.5f * ((float)NANCH - pc));
                bbox_sum += bb;
                cls_sum  += fls / fmaxf(pc * (float)NCLS, 1.0f);
                num_pos  += pc;
            }
            num_pos = fmaxf(num_pos, 1.0f);
            out[0] = obj_sum / (float)NIMG
                   + 5.0f * bbox_sum / num_pos
                   + cls_sum / (float)NIMG;
            g_count = 0;   // reset for next graph replay
        }
    }
}

extern "C" void kernel_launch(void* const* d_in, const int* in_sizes, int n_in,
                              void* d_out, int out_size) {
    const float* obj   = (const float*)d_in[0];
    const float* boxes = (const float*)d_in[1];
    const float* cls   = (const float*)d_in[2];
    const float* tbox  = (const float*)d_in[3];
    const int*   tlab  = (const int*)d_in[4];
    float* out = (float*)d_out;

    loss_fused<<<NBLOCKS, THREADS>>>(obj, boxes, cls, tbox, tlab, out);
}